// round 12
// baseline (speedup 1.0000x reference)
#include <cuda_runtime.h>
#include <math.h>

// B=16, T=4, C=2048, 16 heads / 4 kv heads, d=128, S_cache=4096,
// window=2048, sink=4 -> 2052 effective keys.
// Keys 0..2047 (4 sink + 2044 window) handled by 8 attention splits;
// the 4 NEW keys are folded into combine_kernel as an exact fp32 merge.

#define QKV_KS 16    // k-split for QKV gemm (K-chunk 128, 4 slabs)
#define PROJ_KS 16   // k-split for out-proj gemm (K-chunk 128, 4 slabs)
#define NSPLITS 8    // 8 x 256 cached keys (new keys handled in combine)

__device__ float g_qkv[64 * 3072];     // atomically accumulated QKV
__device__ float g_q[64 * 2048];
__device__ float g_k[64 * 512];
__device__ float g_v[64 * 512];
__device__ float g_po[64 * NSPLITS * 16 * 128];
__device__ float g_pm[64 * NSPLITS * 16];
__device__ float g_pl[64 * NSPLITS * 16];
__device__ float g_y[64 * 2048];

__device__ __forceinline__ unsigned f2tf(float x) {
    unsigned r;
    asm("cvt.rna.tf32.f32 %0, %1;" : "=r"(r) : "f"(x));
    return r;
}
__device__ __forceinline__ void mma_tf32(float* d,
                                         unsigned a0, unsigned a1,
                                         unsigned a2, unsigned a3,
                                         unsigned b0, unsigned b1) {
    asm("mma.sync.aligned.m16n8k8.row.col.f32.tf32.tf32.f32 "
        "{%0,%1,%2,%3}, {%4,%5,%6,%7}, {%8,%9}, {%0,%1,%2,%3};"
        : "+f"(d[0]), "+f"(d[1]), "+f"(d[2]), "+f"(d[3])
        : "r"(a0), "r"(a1), "r"(a2), "r"(a3), "r"(b0), "r"(b1));
}
__device__ __forceinline__ unsigned sptr(const void* p) {
    return (unsigned)__cvta_generic_to_shared(p);
}
#define CPA16(dst, src) \
    asm volatile("cp.async.cg.shared.global [%0], [%1], 16;" :: "r"(dst), "l"(src))
#define CPC() asm volatile("cp.async.commit_group;")
#define CPW1() asm volatile("cp.async.wait_group 1;")
#define CPW0() asm volatile("cp.async.wait_group 0;")

// ---------------------------------------------------------------------------
// Tensor-core GEMM, 3-term tf32 split, cp.async double-buffered W slabs.
// CTA: 64 tokens x 128 cols; nslab = Kchunk/32 = 4.
// Output is ALWAYS atomicAdd into P[token*Pn + col] (P pre-zeroed).
// ---------------------------------------------------------------------------
__global__ void __launch_bounds__(256)
gemm_tf32(const float* __restrict__ X,
          const float* __restrict__ wa,
          const float* __restrict__ wb,
          const float* __restrict__ wc,
          float* __restrict__ P, int Pn, int qkv, int nslab) {
    const int tid = threadIdx.x;
    const int ct = blockIdx.x, ks = blockIdx.y;
    const float* W;
    int Wn, Wc, ob;
    if (qkv) {
        if (ct < 16)      { W = wa; Wn = 2048; Wc = ct * 128;        ob = Wc; }
        else if (ct < 20) { W = wb; Wn = 512;  Wc = (ct - 16) * 128; ob = 2048 + Wc; }
        else              { W = wc; Wn = 512;  Wc = (ct - 20) * 128; ob = 2560 + Wc; }
    } else { W = wa; Wn = 2048; Wc = ct * 128; ob = Wc; }
    const int k0 = ks * nslab * 32;

    __shared__ float xf[2048];           // X slab, fragment order, raw fp32
    __shared__ float ws[2][32 * 136];    // W slabs (double-buffered, raw)

    const int w = tid >> 5, lane = tid & 31;
    const int mt = w & 3, nh = w >> 2;

    float acc[8][4];
#pragma unroll
    for (int i = 0; i < 8; i++)
#pragma unroll
        for (int j = 0; j < 4; j++) acc[i][j] = 0.f;

    const int srow[4] = { tid >> 5, (tid + 256) >> 5, (tid + 512) >> 5, (tid + 768) >> 5 };
    const int sc4 = (tid & 31) * 4;

#pragma unroll
    for (int it = 0; it < 4; it++)
        CPA16(sptr(&ws[0][srow[it] * 136 + sc4]),
              W + (size_t)(k0 + srow[it]) * Wn + Wc + sc4);
    CPC();
    if (nslab > 1) {
#pragma unroll
        for (int it = 0; it < 4; it++)
            CPA16(sptr(&ws[1][srow[it] * 136 + sc4]),
                  W + (size_t)(k0 + 32 + srow[it]) * Wn + Wc + sc4);
        CPC();
    }

#pragma unroll 1
    for (int sl = 0; sl < nslab; sl++) {
        if (sl + 1 < nslab) CPW1(); else CPW0();
        __syncthreads();
        // stage X slab in fragment order (raw fp32)
#pragma unroll
        for (int bb = 0; bb < 2; bb++) {
            int blk = w * 2 + bb;
            int ks4 = blk >> 2, mtb = blk & 3;
            float tmp[4];
#pragma unroll
            for (int j = 0; j < 4; j++) {
                int row = mtb * 16 + (lane >> 2) + (j & 1) * 8;
                int col = ks4 * 8 + (lane & 3) + (j >> 1) * 4;
                tmp[j] = X[row * 2048 + k0 + sl * 32 + col];
            }
            *(float4*)(xf + blk * 128 + lane * 4) =
                make_float4(tmp[0], tmp[1], tmp[2], tmp[3]);
        }
        __syncthreads();

        const float* wsl = ws[sl & 1];
#pragma unroll
        for (int k4 = 0; k4 < 4; k4++) {
            float4 ar = *(const float4*)(xf + (k4 * 4 + mt) * 128 + lane * 4);
            unsigned ah0 = f2tf(ar.x), ah1 = f2tf(ar.y);
            unsigned ah2 = f2tf(ar.z), ah3 = f2tf(ar.w);
            unsigned al0 = f2tf(ar.x - __uint_as_float(ah0));
            unsigned al1 = f2tf(ar.y - __uint_as_float(ah1));
            unsigned al2 = f2tf(ar.z - __uint_as_float(ah2));
            unsigned al3 = f2tf(ar.w - __uint_as_float(ah3));
            const float* wbase = wsl + (k4 * 8 + (lane & 3)) * 136
                               + nh * 64 + (lane >> 2);
#pragma unroll
            for (int nt = 0; nt < 8; nt++) {
                float b0 = wbase[nt * 8];
                float b1 = wbase[nt * 8 + 4 * 136];
                unsigned bh0 = f2tf(b0), bh1 = f2tf(b1);
                unsigned bl0 = f2tf(b0 - __uint_as_float(bh0));
                unsigned bl1 = f2tf(b1 - __uint_as_float(bh1));
                mma_tf32(acc[nt], ah0, ah1, ah2, ah3, bh0, bh1);
                mma_tf32(acc[nt], ah0, ah1, ah2, ah3, bl0, bl1);
                mma_tf32(acc[nt], al0, al1, al2, al3, bh0, bh1);
            }
        }
        __syncthreads();
        if (sl + 2 < nslab) {
#pragma unroll
            for (int it = 0; it < 4; it++)
                CPA16(sptr(&ws[sl & 1][srow[it] * 136 + sc4]),
                      W + (size_t)(k0 + (sl + 2) * 32 + srow[it]) * Wn + Wc + sc4);
            CPC();
        }
    }
    {
        int r = lane >> 2, c2 = (lane & 3) * 2;
#pragma unroll
        for (int nt = 0; nt < 8; nt++) {
            int col = ob + nh * 64 + nt * 8 + c2;
            float* d0 = P + (size_t)(mt * 16 + r) * Pn + col;
            atomicAdd(d0, acc[nt][0]);
            atomicAdd(d0 + 1, acc[nt][1]);
            float* d1 = P + (size_t)(mt * 16 + r + 8) * Pn + col;
            atomicAdd(d1, acc[nt][2]);
            atomicAdd(d1 + 1, acc[nt][3]);
        }
    }
}

// ---------------------------------------------------------------------------
// RoPE-apply: read summed QKV (0.75MB), apply rotation, scatter to g_q/g_k/g_v.
// Inline fp64-angle trig (R8-validated). 64 tokens x 1536 pairs.
// ---------------------------------------------------------------------------
__global__ void reduce_rope_kernel(const int* __restrict__ sp) {
    int gid = blockIdx.x * 256 + threadIdx.x;
    if (gid >= 64 * 1536) return;
    int token = gid / 1536;
    int r = gid - token * 1536;
    int t = token & 3;

    int h, i, c1;
    bool is_q = (r < 1024), is_k = (!is_q && r < 1280);
    if (is_q)      { h = r >> 6;              i = r & 63; c1 = h * 128 + i; }
    else if (is_k) { int rr = r - 1024; h = rr >> 6; i = rr & 63; c1 = 2048 + h * 128 + i; }
    else           { int rr = r - 1280; h = rr >> 6; i = rr & 63; c1 = 2560 + h * 128 + i; }

    float s1 = g_qkv[token * 3072 + c1];
    float s2 = g_qkv[token * 3072 + c1 + 64];

    if (!is_q && !is_k) {
        g_v[token * 512 + h * 128 + i] = s1;
        g_v[token * 512 + h * 128 + i + 64] = s2;
        return;
    }
    int pos = sp[0] + t;
    double invf = exp2(-(double)i * (13.287712379549449 / 64.0));
    double ang = (double)pos * invf;
    double k2 = rint(ang * 0.15915494309189535);
    float angr = (float)(ang - k2 * 6.283185307179586);
    float sn, cs;
    sincosf(angr, &sn, &cs);
    float o1 = s1 * cs - s2 * sn;
    float o2 = s1 * sn + s2 * cs;
    if (is_q) {
        g_q[token * 2048 + c1] = o1;
        g_q[token * 2048 + c1 + 64] = o2;
    } else {
        int cc = h * 128 + i;
        g_k[token * 512 + cc] = o1;
        g_k[token * 512 + cc + 64] = o2;
    }
}

// ---------------------------------------------------------------------------
// Attention (EXACT R10 config — 38.2us proven), mma tf32, async KV streaming.
// Pass1: 8 slabs of 16 d over 256 keys, K frag buffers 2x4096 (depth 1).
// Pass2: 8 tiles of 32 V rows [32][136], 2x4352 double-buffered.
// smem: q_frag 2048 + at_s 4192 + m/l 32 + kv 8704 = 14976 floats (59.9KB)
// ---------------------------------------------------------------------------
#define ATS 262
#define ATTN_SMEM_FLOATS (2048 + 4192 + 32 + 8704)
#define ATTN_SMEM_BYTES (ATTN_SMEM_FLOATS * 4)

__global__ void __launch_bounds__(256, 3)
attn_kernel(const float* __restrict__ ck, const float* __restrict__ cv) {
    extern __shared__ float sm[];
    float* q_frag = sm;                // [16 ksteps][128]
    float* at_s   = sm + 2048;         // [16][262]
    float* m_s    = at_s + 4192;
    float* l_s    = m_s + 16;
    float* kv_s   = l_s + 16;          // K: 2x4096 ; V: 2x4352

    const int tid = threadIdx.x;
    const int split = blockIdx.x & 7;
    const int pair  = blockIdx.x >> 3;
    const int b = pair >> 2, kvh = pair & 3;
    const float scale = 0.08838834764831845f;
    const int w = tid >> 5, lane = tid & 31;

    const float* cbk = ck + (size_t)(b * 4 + kvh) * 4096 * 128;
    const float* cbv = cv + (size_t)(b * 4 + kvh) * 4096 * 128;

    // ---- pass1 staging geometry: thread covers key(w,r), quad q=lane&3 ----
    const int q4 = lane & 3;
    const float* kp[4];
    unsigned kdst[4];
#pragma unroll
    for (int r = 0; r < 4; r++) {
        int key = w * 32 + r * 8 + (lane >> 2);
        int se = split * 256 + key;
        int crow = (se < 4) ? se : se + 2048;
        kp[r] = cbk + (size_t)crow * 128 + q4 * 4;
        int off = (w * 4 + r) * 128 + (q4 >> 1) * 64 + (q4 & 1) * 32
                + (((lane >> 2) ^ q4) & 7) * 4;
        kdst[r] = sptr(kv_s + off);
    }

    // prefetch K slabs 0,1
#pragma unroll
    for (int r = 0; r < 4; r++) CPA16(kdst[r], kp[r]);
    CPC();
#pragma unroll
    for (int r = 0; r < 4; r++) CPA16(kdst[r] + 16384, kp[r] + 16);
    CPC();

    // ---- stage Q in A-fragment order (tf32) — overlaps K DMA ----
#pragma unroll
    for (int i = 0; i < 8; i++) {
        int idx = tid + i * 256;
        int ks = idx >> 7, rem = idx & 127;
        int tl = rem >> 2, j = rem & 3;
        int row = (tl >> 2) + (j & 1) * 8;
        int col = ks * 8 + (tl & 3) + (j >> 1) * 4;
        int hg = row >> 2, t = row & 3;
        float v = g_q[(b * 4 + t) * 2048 + (kvh * 4 + hg) * 128 + col];
        q_frag[idx] = __uint_as_float(f2tf(v));
    }

    // ---- Pass 1: 8 slabs of 16 d ----
    float acc[4][4];
#pragma unroll
    for (int i = 0; i < 4; i++)
#pragma unroll
        for (int j = 0; j < 4; j++) acc[i][j] = 0.f;

#pragma unroll 1
    for (int s = 0; s < 8; s++) {
        if (s < 7) CPW1(); else CPW0();
        __syncthreads();
        const float* kb = kv_s + (s & 1) * 4096;
#pragma unroll
        for (int ksl = 0; ksl < 2; ksl++) {
            uint4 A = *(const uint4*)(q_frag + (s * 2 + ksl) * 128 + lane * 4);
#pragma unroll
            for (int nt = 0; nt < 4; nt++) {
                const float* fb = kb + (w * 4 + nt) * 128 + ksl * 64;
                unsigned bb0 = f2tf(
                    fb[((((lane >> 2) ^ (2 * ksl)) & 7) << 2) + (lane & 3)]);
                unsigned bb1 = f2tf(
                    fb[32 + ((((lane >> 2) ^ (2 * ksl + 1)) & 7) << 2) + (lane & 3)]);
                mma_tf32(acc[nt], A.x, A.y, A.z, A.w, bb0, bb1);
            }
        }
        __syncthreads();
        if (s + 2 < 8) {
#pragma unroll
            for (int r = 0; r < 4; r++)
                CPA16(kdst[r] + (s & 1) * 16384, kp[r] + (s + 2) * 16);
            CPC();
        }
    }
    // write scores
    {
        int r0 = lane >> 2, c2 = (lane & 3) * 2;
#pragma unroll
        for (int nt = 0; nt < 4; nt++) {
            int cc = w * 32 + nt * 8 + c2;
            *(float2*)(at_s + r0 * ATS + cc) =
                make_float2(acc[nt][0] * scale, acc[nt][1] * scale);
            *(float2*)(at_s + (r0 + 8) * ATS + cc) =
                make_float2(acc[nt][2] * scale, acc[nt][3] * scale);
        }
    }
    __syncthreads();   // scores visible; all K reads complete (V reuses region)

    // ---- issue V tiles 0,1 — DMA overlaps softmax ----
#pragma unroll
    for (int rr = 0; rr < 4; rr++) {
        int se = split * 256 + w * 4 + rr;
        int crow = (se < 4) ? se : se + 2048;
        CPA16(sptr(kv_s + (w * 4 + rr) * 136 + lane * 4),
              cbv + (size_t)crow * 128 + lane * 4);
    }
    CPC();
#pragma unroll
    for (int rr = 0; rr < 4; rr++) {
        int se = split * 256 + 32 + w * 4 + rr;
        int crow = (se < 4) ? se : se + 2048;
        CPA16(sptr(kv_s + 4352 + (w * 4 + rr) * 136 + lane * 4),
              cbv + (size_t)crow * 128 + lane * 4);
    }
    CPC();

    // ---- softmax: warp w owns rows 2w, 2w+1 ; store P as tf32 ----
    {
#pragma unroll
        for (int rr = 0; rr < 2; rr++) {
            int r = w * 2 + rr;
            float* row = at_s + r * ATS;
            float m = -3.0e38f;
            for (int sx = lane; sx < 256; sx += 32) m = fmaxf(m, row[sx]);
#pragma unroll
            for (int off = 16; off; off >>= 1)
                m = fmaxf(m, __shfl_xor_sync(0xffffffffu, m, off));
            float l = 0.f;
            for (int sx = lane; sx < 256; sx += 32) {
                float e = __expf(row[sx] - m);
                row[sx] = __uint_as_float(f2tf(e));
                l += e;
            }
#pragma unroll
            for (int off = 16; off; off >>= 1)
                l += __shfl_xor_sync(0xffffffffu, l, off);
            if (lane == 0) { m_s[r] = m; l_s[r] = l; }
        }
    }

    // ---- Pass 2: O = P @ V ; warp w owns d cols w*16..w*16+15 ----
    float oacc[2][4];
#pragma unroll
    for (int i = 0; i < 2; i++)
#pragma unroll
        for (int j = 0; j < 4; j++) oacc[i][j] = 0.f;

#pragma unroll 1
    for (int t = 0; t < 8; t++) {
        if (t < 7) CPW1(); else CPW0();
        __syncthreads();
        const float* vb = kv_s + (t & 1) * 4352;
#pragma unroll
        for (int j = 0; j < 4; j++) {
            const float* pr = at_s + (lane >> 2) * ATS + t * 32 + j * 8 + (lane & 3);
            unsigned a0 = __float_as_uint(pr[0]);
            unsigned a2 = __float_as_uint(pr[4]);
            unsigned a1 = __float_as_uint(pr[8 * ATS]);
            unsigned a3 = __float_as_uint(pr[8 * ATS + 4]);
            const float* vp = vb + (j * 8 + (lane & 3)) * 136 + w * 16 + (lane >> 2);
#pragma unroll
            for (int nt = 0; nt < 2; nt++) {
                unsigned bb0 = f2tf(vp[nt * 8]);
                unsigned bb1 = f2tf(vp[4 * 136 + nt * 8]);
                mma_tf32(oacc[nt], a0, a1, a2, a3, bb0, bb1);
            }
        }
        __syncthreads();
        if (t + 2 < 8) {
#pragma unroll
            for (int rr = 0; rr < 4; rr++) {
                int se = split * 256 + (t + 2) * 32 + w * 4 + rr;
                int crow = (se < 4) ? se : se + 2048;
                CPA16(sptr(kv_s + (t & 1) * 4352 + (w * 4 + rr) * 136 + lane * 4),
                      cbv + (size_t)crow * 128 + lane * 4);
            }
            CPC();
        }
    }

    // write partials + stats
    {
        size_t base = (size_t)(pair * NSPLITS + split) * 16;
        int r0 = lane >> 2, c2 = (lane & 3) * 2;
#pragma unroll
        for (int nt = 0; nt < 2; nt++) {
            int cc = w * 16 + nt * 8 + c2;
            *(float2*)(g_po + (base + r0) * 128 + cc) =
                make_float2(oacc[nt][0], oacc[nt][1]);
            *(float2*)(g_po + (base + r0 + 8) * 128 + cc) =
                make_float2(oacc[nt][2], oacc[nt][3]);
        }
        if (tid < 16) {
            g_pm[base + tid] = m_s[tid];
            g_pl[base + tid] = l_s[tid];
        }
    }
}

// ---------------------------------------------------------------------------
// Combine: merge 8 cached splits + compute the 4 NEW keys exactly (fp32).
// block = (pair*16 + q), 128 threads = d.
// ---------------------------------------------------------------------------
__global__ void combine_kernel() {
    int bidx = blockIdx.x;
    int pair = bidx >> 4, q = bidx & 15;
    int d = threadIdx.x;
    int hg = q >> 2, t = q & 3;
    int b = pair >> 2, kvh = pair & 3;
    int lane = d & 31, w = d >> 5;

    __shared__ float red[4][4];   // [warp][key j]
    __shared__ float sj_s[4];

    const float scale = 0.08838834764831845f;
    float qv = g_q[(b * 4 + t) * 2048 + (kvh * 4 + hg) * 128 + d];

    // scores for the 4 new keys (block reduction over d)
#pragma unroll
    for (int j = 0; j < 4; j++) {
        float s = qv * g_k[(b * 4 + j) * 512 + kvh * 128 + d];
#pragma unroll
        for (int off = 16; off; off >>= 1)
            s += __shfl_xor_sync(0xffffffffu, s, off);
        if (lane == 0) red[w][j] = s;
    }
    __syncthreads();
    if (d < 4)
        sj_s[d] = (red[0][d] + red[1][d] + red[2][d] + red[3][d]) * scale;
    __syncthreads();

    float s0 = sj_s[0], s1 = sj_s[1], s2 = sj_s[2], s3 = sj_s[3];
    float m_new = fmaxf(fmaxf(s0, s1), fmaxf(s2, s3));
    float e0 = __expf(s0 - m_new), e1 = __expf(s1 - m_new);
    float e2 = __expf(s2 - m_new), e3 = __expf(s3 - m_new);
    float l_new = e0 + e1 + e2 + e3;
    float o_new = e0 * g_v[(b * 4 + 0) * 512 + kvh * 128 + d]
                + e1 * g_v[(b * 4 + 1) * 512 + kvh * 128 + d]
                + e2 * g_v[(b * 4 + 2) * 512 + kvh * 128 + d]
                + e3 * g_v[(b * 4 + 3) * 512 + kvh * 128 + d];

    float ms[NSPLITS];
    float M = m_new;
#pragma unroll
    for (int i = 0; i < NSPLITS; i++) {
        ms[i] = g_pm[(pair * NSPLITS + i) * 16 + q];
        M = fmaxf(M, ms[i]);
    }
    float L = 0.f, acc = 0.f;
#pragma unroll
    for (int i = 0; i < NSPLITS; i++) {
        float wgt = __expf(ms[i] - M);
        L += wgt * g_pl[(pair * NSPLITS + i) * 16 + q];
        acc += wgt * g_po[((size_t)(pair * NSPLITS + i) * 16 + q) * 128 + d];
    }
    float wn = __expf(m_new - M);
    L += wn * l_new;
    acc += wn * o_new;
    g_y[(b * 4 + t) * 2048 + (kvh * 4 + hg) * 128 + d] = acc / L;
}

// ---------------------------------------------------------------------------
extern "C" void kernel_launch(void* const* d_in, const int* in_sizes, int n_in,
                              void* d_out, int out_size) {
    const float* x     = (const float*)d_in[0];
    const float* ck    = (const float*)d_in[1];
    const float* cv    = (const float*)d_in[2];
    const float* wq    = (const float*)d_in[3];
    const float* wk    = (const float*)d_in[4];
    const float* wv    = (const float*)d_in[5];
    const float* wproj = (const float*)d_in[6];
    const int*   sp    = (const int*)d_in[7];
    float* out = (float*)d_out;

    float *qkvp, *yp;
    cudaGetSymbolAddress((void**)&qkvp, g_qkv);
    cudaGetSymbolAddress((void**)&yp, g_y);

    cudaFuncSetAttribute(attn_kernel,
                         cudaFuncAttributeMaxDynamicSharedMemorySize,
                         ATTN_SMEM_BYTES);

    // zero the atomic accumulation targets
    cudaMemsetAsync(d_out, 0, (size_t)out_size * sizeof(float));
    cudaMemsetAsync(qkvp, 0, 64 * 3072 * sizeof(float));

    gemm_tf32<<<dim3(24, QKV_KS), 256>>>(x, wq, wk, wv, qkvp, 3072, 1, 4);
    reduce_rope_kernel<<<384, 256>>>(sp);
    attn_kernel<<<64 * NSPLITS, 256, ATTN_SMEM_BYTES>>>(ck, cv);
    combine_kernel<<<1024, 128>>>();
    gemm_tf32<<<dim3(16, PROJ_KS), 256>>>(yp, wproj, wproj, wproj, out, 2048, 0, 4);
}

// round 13
// speedup vs baseline: 1.0404x; 1.0404x over previous
#include <cuda_runtime.h>
#include <math.h>

// B=16, T=4, C=2048, 16 heads / 4 kv heads, d=128, S_cache=4096,
// window=2048, sink=4 -> 2052 effective keys.
// Keys 0..2047 (4 sink + 2044 window) handled by 8 attention splits;
// the 4 NEW keys are folded into combine_kernel as an exact fp32 merge.

#define QKV_KS 16    // k-split for QKV gemm (K-chunk 128, 4 slabs)
#define PROJ_KS 16   // k-split for out-proj gemm (K-chunk 128, 4 slabs)
#define NSPLITS 8    // 8 x 256 cached keys (new keys handled in combine)

__device__ float g_qkv_part[QKV_KS][64][3072];
__device__ float g_q[64 * 2048];
__device__ float g_k[64 * 512];
__device__ float g_v[64 * 512];
__device__ float g_po[64 * NSPLITS * 16 * 128];
__device__ float g_pm[64 * NSPLITS * 16];
__device__ float g_pl[64 * NSPLITS * 16];
__device__ float g_y[64 * 2048];
__device__ float g_cos[4][64];
__device__ float g_sin[4][64];

__device__ __forceinline__ unsigned f2tf(float x) {
    unsigned r;
    asm("cvt.rna.tf32.f32 %0, %1;" : "=r"(r) : "f"(x));
    return r;
}
__device__ __forceinline__ void mma_tf32(float* d,
                                         unsigned a0, unsigned a1,
                                         unsigned a2, unsigned a3,
                                         unsigned b0, unsigned b1) {
    asm("mma.sync.aligned.m16n8k8.row.col.f32.tf32.tf32.f32 "
        "{%0,%1,%2,%3}, {%4,%5,%6,%7}, {%8,%9}, {%0,%1,%2,%3};"
        : "+f"(d[0]), "+f"(d[1]), "+f"(d[2]), "+f"(d[3])
        : "r"(a0), "r"(a1), "r"(a2), "r"(a3), "r"(b0), "r"(b1));
}
__device__ __forceinline__ unsigned sptr(const void* p) {
    return (unsigned)__cvta_generic_to_shared(p);
}
#define CPA16(dst, src) \
    asm volatile("cp.async.cg.shared.global [%0], [%1], 16;" :: "r"(dst), "l"(src))
#define CPC() asm volatile("cp.async.commit_group;")
#define CPW1() asm volatile("cp.async.wait_group 1;")
#define CPW0() asm volatile("cp.async.wait_group 0;")

// ---------------------------------------------------------------------------
__global__ void rope_table_kernel(const int* __restrict__ sp) {
    int tid = blockIdx.x * 32 + threadIdx.x;
    if (tid >= 256) return;
    int t = tid >> 6, i = tid & 63;
    double f = exp2(-(double)i * (13.287712379549449 / 64.0));
    double ang = (double)(sp[0] + t) * f;
    double s, c;
    sincos(ang, &s, &c);
    g_cos[t][i] = (float)c;
    g_sin[t][i] = (float)s;
}

// ---------------------------------------------------------------------------
// Tensor-core GEMM, 3-term tf32 split, cp.async double-buffered W slabs.
// CTA: 64 tokens x 128 cols; nslab = Kchunk/32 = 4.
// atomic_out=1: accumulate into P (stride Pn) with atomicAdd (P pre-zeroed);
// atomic_out=0: write k-split partials at P[ks*64 + token].
// ---------------------------------------------------------------------------
__global__ void __launch_bounds__(256)
gemm_tf32(const float* __restrict__ X,
          const float* __restrict__ wa,
          const float* __restrict__ wb,
          const float* __restrict__ wc,
          float* __restrict__ P, int Pn, int qkv, int nslab, int atomic_out) {
    const int tid = threadIdx.x;
    const int ct = blockIdx.x, ks = blockIdx.y;
    const float* W;
    int Wn, Wc, ob;
    if (qkv) {
        if (ct < 16)      { W = wa; Wn = 2048; Wc = ct * 128;        ob = Wc; }
        else if (ct < 20) { W = wb; Wn = 512;  Wc = (ct - 16) * 128; ob = 2048 + Wc; }
        else              { W = wc; Wn = 512;  Wc = (ct - 20) * 128; ob = 2560 + Wc; }
    } else { W = wa; Wn = 2048; Wc = ct * 128; ob = Wc; }
    const int k0 = ks * nslab * 32;

    __shared__ float xf[2048];           // X slab, fragment order, raw fp32
    __shared__ float ws[2][32 * 136];    // W slabs (double-buffered, raw)

    const int w = tid >> 5, lane = tid & 31;
    const int mt = w & 3, nh = w >> 2;

    float acc[8][4];
#pragma unroll
    for (int i = 0; i < 8; i++)
#pragma unroll
        for (int j = 0; j < 4; j++) acc[i][j] = 0.f;

    const int srow[4] = { tid >> 5, (tid + 256) >> 5, (tid + 512) >> 5, (tid + 768) >> 5 };
    const int sc4 = (tid & 31) * 4;

#pragma unroll
    for (int it = 0; it < 4; it++)
        CPA16(sptr(&ws[0][srow[it] * 136 + sc4]),
              W + (size_t)(k0 + srow[it]) * Wn + Wc + sc4);
    CPC();
    if (nslab > 1) {
#pragma unroll
        for (int it = 0; it < 4; it++)
            CPA16(sptr(&ws[1][srow[it] * 136 + sc4]),
                  W + (size_t)(k0 + 32 + srow[it]) * Wn + Wc + sc4);
        CPC();
    }

#pragma unroll 1
    for (int sl = 0; sl < nslab; sl++) {
        if (sl + 1 < nslab) CPW1(); else CPW0();
        __syncthreads();
        // stage X slab in fragment order (raw fp32)
#pragma unroll
        for (int bb = 0; bb < 2; bb++) {
            int blk = w * 2 + bb;
            int ks4 = blk >> 2, mtb = blk & 3;
            float tmp[4];
#pragma unroll
            for (int j = 0; j < 4; j++) {
                int row = mtb * 16 + (lane >> 2) + (j & 1) * 8;
                int col = ks4 * 8 + (lane & 3) + (j >> 1) * 4;
                tmp[j] = X[row * 2048 + k0 + sl * 32 + col];
            }
            *(float4*)(xf + blk * 128 + lane * 4) =
                make_float4(tmp[0], tmp[1], tmp[2], tmp[3]);
        }
        __syncthreads();

        const float* wsl = ws[sl & 1];
#pragma unroll
        for (int k4 = 0; k4 < 4; k4++) {
            float4 ar = *(const float4*)(xf + (k4 * 4 + mt) * 128 + lane * 4);
            unsigned ah0 = f2tf(ar.x), ah1 = f2tf(ar.y);
            unsigned ah2 = f2tf(ar.z), ah3 = f2tf(ar.w);
            unsigned al0 = f2tf(ar.x - __uint_as_float(ah0));
            unsigned al1 = f2tf(ar.y - __uint_as_float(ah1));
            unsigned al2 = f2tf(ar.z - __uint_as_float(ah2));
            unsigned al3 = f2tf(ar.w - __uint_as_float(ah3));
            const float* wbase = wsl + (k4 * 8 + (lane & 3)) * 136
                               + nh * 64 + (lane >> 2);
#pragma unroll
            for (int nt = 0; nt < 8; nt++) {
                float b0 = wbase[nt * 8];
                float b1 = wbase[nt * 8 + 4 * 136];
                unsigned bh0 = f2tf(b0), bh1 = f2tf(b1);
                unsigned bl0 = f2tf(b0 - __uint_as_float(bh0));
                unsigned bl1 = f2tf(b1 - __uint_as_float(bh1));
                mma_tf32(acc[nt], ah0, ah1, ah2, ah3, bh0, bh1);
                mma_tf32(acc[nt], ah0, ah1, ah2, ah3, bl0, bl1);
                mma_tf32(acc[nt], al0, al1, al2, al3, bh0, bh1);
            }
        }
        __syncthreads();
        if (sl + 2 < nslab) {
#pragma unroll
            for (int it = 0; it < 4; it++)
                CPA16(sptr(&ws[sl & 1][srow[it] * 136 + sc4]),
                      W + (size_t)(k0 + (sl + 2) * 32 + srow[it]) * Wn + Wc + sc4);
            CPC();
        }
    }
    {
        int r = lane >> 2, c2 = (lane & 3) * 2;
        if (atomic_out) {
#pragma unroll
            for (int nt = 0; nt < 8; nt++) {
                int col = ob + nh * 64 + nt * 8 + c2;
                float* d0 = P + (size_t)(mt * 16 + r) * Pn + col;
                atomicAdd(d0, acc[nt][0]);
                atomicAdd(d0 + 1, acc[nt][1]);
                float* d1 = P + (size_t)(mt * 16 + r + 8) * Pn + col;
                atomicAdd(d1, acc[nt][2]);
                atomicAdd(d1 + 1, acc[nt][3]);
            }
        } else {
#pragma unroll
            for (int nt = 0; nt < 8; nt++) {
                int col = ob + nh * 64 + nt * 8 + c2;
                *(float2*)(P + ((size_t)ks * 64 + mt * 16 + r) * Pn + col) =
                    make_float2(acc[nt][0], acc[nt][1]);
                *(float2*)(P + ((size_t)ks * 64 + mt * 16 + r + 8) * Pn + col) =
                    make_float2(acc[nt][2], acc[nt][3]);
            }
        }
    }
}

// ---------------------------------------------------------------------------
// Reduce QKV k-split partials + fused RoPE (table-based trig — R10 proven).
// ---------------------------------------------------------------------------
__global__ void reduce_rope_kernel() {
    int gid = blockIdx.x * 256 + threadIdx.x;
    if (gid >= 64 * 1536) return;
    int token = gid / 1536;
    int r = gid - token * 1536;
    int t = token & 3;
    const float* P = &g_qkv_part[0][0][0];

    int h, i, c1;
    bool is_q = (r < 1024), is_k = (!is_q && r < 1280);
    if (is_q)      { h = r >> 6;              i = r & 63; c1 = h * 128 + i; }
    else if (is_k) { int rr = r - 1024; h = rr >> 6; i = rr & 63; c1 = 2048 + h * 128 + i; }
    else           { int rr = r - 1280; h = rr >> 6; i = rr & 63; c1 = 2560 + h * 128 + i; }

    float s1 = 0.f, s2 = 0.f;
#pragma unroll
    for (int ks = 0; ks < QKV_KS; ks++) {
        const float* row = P + ((size_t)ks * 64 + token) * 3072;
        s1 += row[c1];
        s2 += row[c1 + 64];
    }
    if (!is_q && !is_k) {
        g_v[token * 512 + h * 128 + i] = s1;
        g_v[token * 512 + h * 128 + i + 64] = s2;
        return;
    }
    float cs = g_cos[t][i], sn = g_sin[t][i];
    float o1 = s1 * cs - s2 * sn;
    float o2 = s1 * sn + s2 * cs;
    if (is_q) {
        g_q[token * 2048 + c1] = o1;
        g_q[token * 2048 + c1 + 64] = o2;
    } else {
        int cc = h * 128 + i;
        g_k[token * 512 + cc] = o1;
        g_k[token * 512 + cc + 64] = o2;
    }
}

// ---------------------------------------------------------------------------
// Attention (EXACT R10 config — 38.2us measured), mma tf32, async KV stream.
// Pass1: 8 slabs of 16 d over 256 keys, K frag buffers 2x4096 (depth 1).
// Pass2: 8 tiles of 32 V rows [32][136], 2x4352 double-buffered.
// smem: q_frag 2048 + at_s 4192 + m/l 32 + kv 8704 = 14976 floats (59.9KB)
// ---------------------------------------------------------------------------
#define ATS 262
#define ATTN_SMEM_FLOATS (2048 + 4192 + 32 + 8704)
#define ATTN_SMEM_BYTES (ATTN_SMEM_FLOATS * 4)

__global__ void __launch_bounds__(256, 3)
attn_kernel(const float* __restrict__ ck, const float* __restrict__ cv) {
    extern __shared__ float sm[];
    float* q_frag = sm;                // [16 ksteps][128]
    float* at_s   = sm + 2048;         // [16][262]
    float* m_s    = at_s + 4192;
    float* l_s    = m_s + 16;
    float* kv_s   = l_s + 16;          // K: 2x4096 ; V: 2x4352

    const int tid = threadIdx.x;
    const int split = blockIdx.x & 7;
    const int pair  = blockIdx.x >> 3;
    const int b = pair >> 2, kvh = pair & 3;
    const float scale = 0.08838834764831845f;
    const int w = tid >> 5, lane = tid & 31;

    const float* cbk = ck + (size_t)(b * 4 + kvh) * 4096 * 128;
    const float* cbv = cv + (size_t)(b * 4 + kvh) * 4096 * 128;

    // ---- pass1 staging geometry: thread covers key(w,r), quad q=lane&3 ----
    const int q4 = lane & 3;
    const float* kp[4];
    unsigned kdst[4];
#pragma unroll
    for (int r = 0; r < 4; r++) {
        int key = w * 32 + r * 8 + (lane >> 2);
        int se = split * 256 + key;
        int crow = (se < 4) ? se : se + 2048;
        kp[r] = cbk + (size_t)crow * 128 + q4 * 4;
        int off = (w * 4 + r) * 128 + (q4 >> 1) * 64 + (q4 & 1) * 32
                + (((lane >> 2) ^ q4) & 7) * 4;
        kdst[r] = sptr(kv_s + off);
    }

    // prefetch K slabs 0,1
#pragma unroll
    for (int r = 0; r < 4; r++) CPA16(kdst[r], kp[r]);
    CPC();
#pragma unroll
    for (int r = 0; r < 4; r++) CPA16(kdst[r] + 16384, kp[r] + 16);
    CPC();

    // ---- stage Q in A-fragment order (tf32) — overlaps K DMA ----
#pragma unroll
    for (int i = 0; i < 8; i++) {
        int idx = tid + i * 256;
        int ks = idx >> 7, rem = idx & 127;
        int tl = rem >> 2, j = rem & 3;
        int row = (tl >> 2) + (j & 1) * 8;
        int col = ks * 8 + (tl & 3) + (j >> 1) * 4;
        int hg = row >> 2, t = row & 3;
        float v = g_q[(b * 4 + t) * 2048 + (kvh * 4 + hg) * 128 + col];
        q_frag[idx] = __uint_as_float(f2tf(v));
    }

    // ---- Pass 1: 8 slabs of 16 d ----
    float acc[4][4];
#pragma unroll
    for (int i = 0; i < 4; i++)
#pragma unroll
        for (int j = 0; j < 4; j++) acc[i][j] = 0.f;

#pragma unroll 1
    for (int s = 0; s < 8; s++) {
        if (s < 7) CPW1(); else CPW0();
        __syncthreads();
        const float* kb = kv_s + (s & 1) * 4096;
#pragma unroll
        for (int ksl = 0; ksl < 2; ksl++) {
            uint4 A = *(const uint4*)(q_frag + (s * 2 + ksl) * 128 + lane * 4);
#pragma unroll
            for (int nt = 0; nt < 4; nt++) {
                const float* fb = kb + (w * 4 + nt) * 128 + ksl * 64;
                unsigned bb0 = f2tf(
                    fb[((((lane >> 2) ^ (2 * ksl)) & 7) << 2) + (lane & 3)]);
                unsigned bb1 = f2tf(
                    fb[32 + ((((lane >> 2) ^ (2 * ksl + 1)) & 7) << 2) + (lane & 3)]);
                mma_tf32(acc[nt], A.x, A.y, A.z, A.w, bb0, bb1);
            }
        }
        __syncthreads();
        if (s + 2 < 8) {
#pragma unroll
            for (int r = 0; r < 4; r++)
                CPA16(kdst[r] + (s & 1) * 16384, kp[r] + (s + 2) * 16);
            CPC();
        }
    }
    // write scores
    {
        int r0 = lane >> 2, c2 = (lane & 3) * 2;
#pragma unroll
        for (int nt = 0; nt < 4; nt++) {
            int cc = w * 32 + nt * 8 + c2;
            *(float2*)(at_s + r0 * ATS + cc) =
                make_float2(acc[nt][0] * scale, acc[nt][1] * scale);
            *(float2*)(at_s + (r0 + 8) * ATS + cc) =
                make_float2(acc[nt][2] * scale, acc[nt][3] * scale);
        }
    }
    __syncthreads();   // scores visible; all K reads complete (V reuses region)

    // ---- issue V tiles 0,1 — DMA overlaps softmax ----
#pragma unroll
    for (int rr = 0; rr < 4; rr++) {
        int se = split * 256 + w * 4 + rr;
        int crow = (se < 4) ? se : se + 2048;
        CPA16(sptr(kv_s + (w * 4 + rr) * 136 + lane * 4),
              cbv + (size_t)crow * 128 + lane * 4);
    }
    CPC();
#pragma unroll
    for (int rr = 0; rr < 4; rr++) {
        int se = split * 256 + 32 + w * 4 + rr;
        int crow = (se < 4) ? se : se + 2048;
        CPA16(sptr(kv_s + 4352 + (w * 4 + rr) * 136 + lane * 4),
              cbv + (size_t)crow * 128 + lane * 4);
    }
    CPC();

    // ---- softmax: warp w owns rows 2w, 2w+1 ; store P as tf32 ----
    {
#pragma unroll
        for (int rr = 0; rr < 2; rr++) {
            int r = w * 2 + rr;
            float* row = at_s + r * ATS;
            float m = -3.0e38f;
            for (int sx = lane; sx < 256; sx += 32) m = fmaxf(m, row[sx]);
#pragma unroll
            for (int off = 16; off; off >>= 1)
                m = fmaxf(m, __shfl_xor_sync(0xffffffffu, m, off));
            float l = 0.f;
            for (int sx = lane; sx < 256; sx += 32) {
                float e = __expf(row[sx] - m);
                row[sx] = __uint_as_float(f2tf(e));
                l += e;
            }
#pragma unroll
            for (int off = 16; off; off >>= 1)
                l += __shfl_xor_sync(0xffffffffu, l, off);
            if (lane == 0) { m_s[r] = m; l_s[r] = l; }
        }
    }

    // ---- Pass 2: O = P @ V ; warp w owns d cols w*16..w*16+15 ----
    float oacc[2][4];
#pragma unroll
    for (int i = 0; i < 2; i++)
#pragma unroll
        for (int j = 0; j < 4; j++) oacc[i][j] = 0.f;

#pragma unroll 1
    for (int t = 0; t < 8; t++) {
        if (t < 7) CPW1(); else CPW0();
        __syncthreads();
        const float* vb = kv_s + (t & 1) * 4352;
#pragma unroll
        for (int j = 0; j < 4; j++) {
            const float* pr = at_s + (lane >> 2) * ATS + t * 32 + j * 8 + (lane & 3);
            unsigned a0 = __float_as_uint(pr[0]);
            unsigned a2 = __float_as_uint(pr[4]);
            unsigned a1 = __float_as_uint(pr[8 * ATS]);
            unsigned a3 = __float_as_uint(pr[8 * ATS + 4]);
            const float* vp = vb + (j * 8 + (lane & 3)) * 136 + w * 16 + (lane >> 2);
#pragma unroll
            for (int nt = 0; nt < 2; nt++) {
                unsigned bb0 = f2tf(vp[nt * 8]);
                unsigned bb1 = f2tf(vp[4 * 136 + nt * 8]);
                mma_tf32(oacc[nt], a0, a1, a2, a3, bb0, bb1);
            }
        }
        __syncthreads();
        if (t + 2 < 8) {
#pragma unroll
            for (int rr = 0; rr < 4; rr++) {
                int se = split * 256 + (t + 2) * 32 + w * 4 + rr;
                int crow = (se < 4) ? se : se + 2048;
                CPA16(sptr(kv_s + (t & 1) * 4352 + (w * 4 + rr) * 136 + lane * 4),
                      cbv + (size_t)crow * 128 + lane * 4);
            }
            CPC();
        }
    }

    // write partials + stats
    {
        size_t base = (size_t)(pair * NSPLITS + split) * 16;
        int r0 = lane >> 2, c2 = (lane & 3) * 2;
#pragma unroll
        for (int nt = 0; nt < 2; nt++) {
            int cc = w * 16 + nt * 8 + c2;
            *(float2*)(g_po + (base + r0) * 128 + cc) =
                make_float2(oacc[nt][0], oacc[nt][1]);
            *(float2*)(g_po + (base + r0 + 8) * 128 + cc) =
                make_float2(oacc[nt][2], oacc[nt][3]);
        }
        if (tid < 16) {
            g_pm[base + tid] = m_s[tid];
            g_pl[base + tid] = l_s[tid];
        }
    }
}

// ---------------------------------------------------------------------------
// Combine: merge 8 cached splits + compute the 4 NEW keys exactly (fp32).
// block = (pair*16 + q), 128 threads = d.
// ---------------------------------------------------------------------------
__global__ void combine_kernel() {
    int bidx = blockIdx.x;
    int pair = bidx >> 4, q = bidx & 15;
    int d = threadIdx.x;
    int hg = q >> 2, t = q & 3;
    int b = pair >> 2, kvh = pair & 3;
    int lane = d & 31, w = d >> 5;

    __shared__ float red[4][4];   // [warp][key j]
    __shared__ float sj_s[4];

    const float scale = 0.08838834764831845f;
    float qv = g_q[(b * 4 + t) * 2048 + (kvh * 4 + hg) * 128 + d];

    // scores for the 4 new keys (block reduction over d)
#pragma unroll
    for (int j = 0; j < 4; j++) {
        float s = qv * g_k[(b * 4 + j) * 512 + kvh * 128 + d];
#pragma unroll
        for (int off = 16; off; off >>= 1)
            s += __shfl_xor_sync(0xffffffffu, s, off);
        if (lane == 0) red[w][j] = s;
    }
    __syncthreads();
    if (d < 4)
        sj_s[d] = (red[0][d] + red[1][d] + red[2][d] + red[3][d]) * scale;
    __syncthreads();

    float s0 = sj_s[0], s1 = sj_s[1], s2 = sj_s[2], s3 = sj_s[3];
    float m_new = fmaxf(fmaxf(s0, s1), fmaxf(s2, s3));
    float e0 = __expf(s0 - m_new), e1 = __expf(s1 - m_new);
    float e2 = __expf(s2 - m_new), e3 = __expf(s3 - m_new);
    float l_new = e0 + e1 + e2 + e3;
    float o_new = e0 * g_v[(b * 4 + 0) * 512 + kvh * 128 + d]
                + e1 * g_v[(b * 4 + 1) * 512 + kvh * 128 + d]
                + e2 * g_v[(b * 4 + 2) * 512 + kvh * 128 + d]
                + e3 * g_v[(b * 4 + 3) * 512 + kvh * 128 + d];

    float ms[NSPLITS];
    float M = m_new;
#pragma unroll
    for (int i = 0; i < NSPLITS; i++) {
        ms[i] = g_pm[(pair * NSPLITS + i) * 16 + q];
        M = fmaxf(M, ms[i]);
    }
    float L = 0.f, acc = 0.f;
#pragma unroll
    for (int i = 0; i < NSPLITS; i++) {
        float wgt = __expf(ms[i] - M);
        L += wgt * g_pl[(pair * NSPLITS + i) * 16 + q];
        acc += wgt * g_po[((size_t)(pair * NSPLITS + i) * 16 + q) * 128 + d];
    }
    float wn = __expf(m_new - M);
    L += wn * l_new;
    acc += wn * o_new;
    g_y[(b * 4 + t) * 2048 + (kvh * 4 + hg) * 128 + d] = acc / L;
}

// ---------------------------------------------------------------------------
extern "C" void kernel_launch(void* const* d_in, const int* in_sizes, int n_in,
                              void* d_out, int out_size) {
    const float* x     = (const float*)d_in[0];
    const float* ck    = (const float*)d_in[1];
    const float* cv    = (const float*)d_in[2];
    const float* wq    = (const float*)d_in[3];
    const float* wk    = (const float*)d_in[4];
    const float* wv    = (const float*)d_in[5];
    const float* wproj = (const float*)d_in[6];
    const int*   sp    = (const int*)d_in[7];
    float* out = (float*)d_out;

    float *qkvp, *yp;
    cudaGetSymbolAddress((void**)&qkvp, g_qkv_part);
    cudaGetSymbolAddress((void**)&yp, g_y);

    cudaFuncSetAttribute(attn_kernel,
                         cudaFuncAttributeMaxDynamicSharedMemorySize,
                         ATTN_SMEM_BYTES);

    // zero the output (accumulated atomically by the proj GEMM)
    cudaMemsetAsync(d_out, 0, (size_t)out_size * sizeof(float));

    rope_table_kernel<<<8, 32>>>(sp);
    gemm_tf32<<<dim3(24, QKV_KS), 256>>>(x, wq, wk, wv, qkvp, 3072, 1, 4, 0);
    reduce_rope_kernel<<<384, 256>>>();
    attn_kernel<<<64 * NSPLITS, 256, ATTN_SMEM_BYTES>>>(ck, cv);
    combine_kernel<<<1024, 128>>>();
    gemm_tf32<<<dim3(16, PROJ_KS), 256>>>(yp, wproj, wproj, wproj, out, 2048, 0, 4, 1);
}

// round 14
// speedup vs baseline: 1.2298x; 1.1820x over previous
#include <cuda_runtime.h>
#include <cuda_bf16.h>
#include <math.h>

// B=16, T=4, C=2048, 16 heads / 4 kv heads, d=128, S_cache=4096,
// window=2048, sink=4 -> 2052 effective keys.
// Keys 0..2047 (4 sink + 2044 window) handled by 8 attention splits;
// the 4 NEW keys are folded into combine_kernel as an exact fp32 merge.

#define QKV_KS 16    // k-split for QKV gemm (K-chunk 128, 4 slabs)
#define PROJ_KS 16   // k-split for out-proj gemm (K-chunk 128, 4 slabs)
#define NSPLITS 8    // 8 x 256 cached keys (new keys handled in combine)

__device__ float g_qkv_part[QKV_KS][64][3072];
__device__ float g_q[64 * 2048];
__device__ float g_k[64 * 512];
__device__ float g_v[64 * 512];
__device__ float g_po[64 * NSPLITS * 16 * 128];
__device__ float g_pm[64 * NSPLITS * 16];
__device__ float g_pl[64 * NSPLITS * 16];
__device__ float g_y[64 * 2048];
__device__ float g_cos[4][64];
__device__ float g_sin[4][64];

__device__ __forceinline__ unsigned f2tf(float x) {
    unsigned r;
    asm("cvt.rna.tf32.f32 %0, %1;" : "=r"(r) : "f"(x));
    return r;
}
__device__ __forceinline__ void mma_tf32(float* d,
                                         unsigned a0, unsigned a1,
                                         unsigned a2, unsigned a3,
                                         unsigned b0, unsigned b1) {
    asm("mma.sync.aligned.m16n8k8.row.col.f32.tf32.tf32.f32 "
        "{%0,%1,%2,%3}, {%4,%5,%6,%7}, {%8,%9}, {%0,%1,%2,%3};"
        : "+f"(d[0]), "+f"(d[1]), "+f"(d[2]), "+f"(d[3])
        : "r"(a0), "r"(a1), "r"(a2), "r"(a3), "r"(b0), "r"(b1));
}
__device__ __forceinline__ void mma_bf16(float* d,
                                         unsigned a0, unsigned a1,
                                         unsigned a2, unsigned a3,
                                         unsigned b0, unsigned b1) {
    asm("mma.sync.aligned.m16n8k16.row.col.f32.bf16.bf16.f32 "
        "{%0,%1,%2,%3}, {%4,%5,%6,%7}, {%8,%9}, {%0,%1,%2,%3};"
        : "+f"(d[0]), "+f"(d[1]), "+f"(d[2]), "+f"(d[3])
        : "r"(a0), "r"(a1), "r"(a2), "r"(a3), "r"(b0), "r"(b1));
}
__device__ __forceinline__ unsigned sptr(const void* p) {
    return (unsigned)__cvta_generic_to_shared(p);
}
#define CPA16(dst, src) \
    asm volatile("cp.async.cg.shared.global [%0], [%1], 16;" :: "r"(dst), "l"(src))
#define CPC() asm volatile("cp.async.commit_group;")
#define CPW1() asm volatile("cp.async.wait_group 1;")
#define CPW0() asm volatile("cp.async.wait_group 0;")

// split x into bf16 hi/lo pair, packed as bf16x2 (low half = first element)
__device__ __forceinline__ void bf16_split2(float x0, float x1,
                                            unsigned& hp, unsigned& lp) {
    __nv_bfloat162 h = __floats2bfloat162_rn(x0, x1);
    float l0 = x0 - __bfloat162float(h.x);
    float l1 = x1 - __bfloat162float(h.y);
    __nv_bfloat162 l = __floats2bfloat162_rn(l0, l1);
    hp = *(unsigned*)&h;
    lp = *(unsigned*)&l;
}

// ---------------------------------------------------------------------------
__global__ void rope_table_kernel(const int* __restrict__ sp) {
    int tid = blockIdx.x * 32 + threadIdx.x;
    if (tid >= 256) return;
    int t = tid >> 6, i = tid & 63;
    double f = exp2(-(double)i * (13.287712379549449 / 64.0));
    double ang = (double)(sp[0] + t) * f;
    double s, c;
    sincos(ang, &s, &c);
    g_cos[t][i] = (float)c;
    g_sin[t][i] = (float)s;
}

// ---------------------------------------------------------------------------
// Tensor-core GEMM, 3-term BF16 split (hi*hi + hi*lo + lo*hi), m16n8k16.
// CTA: 64 tokens x 128 cols; nslab = Kchunk/32 = 4; cp.async raw W slabs.
// Per slab: X gathered into bf16x2 fragment order (hi/lo at staging);
// raw W repacked into k-paired bf16x2 hi/lo (conflict-free banks).
// atomic_out=1: atomicAdd into P (pre-zeroed); else k-split partial store.
// smem floats: xh 1024 + xl 1024 + wsraw 2*4352 + wh 2176 + wl 2176 = 15104
// ---------------------------------------------------------------------------
#define GEMM_SMEM_FLOATS 15104
#define GEMM_SMEM_BYTES (GEMM_SMEM_FLOATS * 4)

__global__ void __launch_bounds__(256)
gemm_bf16(const float* __restrict__ X,
          const float* __restrict__ wa,
          const float* __restrict__ wb,
          const float* __restrict__ wc,
          float* __restrict__ P, int Pn, int qkv, int nslab, int atomic_out) {
    extern __shared__ float sm[];
    unsigned* xh = (unsigned*)sm;            // 1024 uints
    unsigned* xl = (unsigned*)(sm + 1024);   // 1024
    float*    wsr = sm + 2048;               // 2 x 32x136 raw
    unsigned* wh = (unsigned*)(sm + 10752);  // 16x136
    unsigned* wl = (unsigned*)(sm + 12928);  // 16x136

    const int tid = threadIdx.x;
    const int ct = blockIdx.x, ks = blockIdx.y;
    const float* W;
    int Wn, Wc, ob;
    if (qkv) {
        if (ct < 16)      { W = wa; Wn = 2048; Wc = ct * 128;        ob = Wc; }
        else if (ct < 20) { W = wb; Wn = 512;  Wc = (ct - 16) * 128; ob = 2048 + Wc; }
        else              { W = wc; Wn = 512;  Wc = (ct - 20) * 128; ob = 2560 + Wc; }
    } else { W = wa; Wn = 2048; Wc = ct * 128; ob = Wc; }
    const int k0 = ks * nslab * 32;

    const int w = tid >> 5, lane = tid & 31;
    const int mt = w & 3, nh = w >> 2;

    float acc[8][4];
#pragma unroll
    for (int i = 0; i < 8; i++)
#pragma unroll
        for (int j = 0; j < 4; j++) acc[i][j] = 0.f;

    const int srow[4] = { tid >> 5, (tid + 256) >> 5, (tid + 512) >> 5, (tid + 768) >> 5 };
    const int sc4 = (tid & 31) * 4;

#pragma unroll
    for (int it = 0; it < 4; it++)
        CPA16(sptr(wsr + srow[it] * 136 + sc4),
              W + (size_t)(k0 + srow[it]) * Wn + Wc + sc4);
    CPC();
    if (nslab > 1) {
#pragma unroll
        for (int it = 0; it < 4; it++)
            CPA16(sptr(wsr + 4352 + srow[it] * 136 + sc4),
                  W + (size_t)(k0 + 32 + srow[it]) * Wn + Wc + sc4);
        CPC();
    }

#pragma unroll 1
    for (int sl = 0; sl < nslab; sl++) {
        if (sl + 1 < nslab) CPW1(); else CPW0();
        __syncthreads();
        // ---- stage X slab: bf16x2 hi/lo in k16 A-fragment order ----
#pragma unroll
        for (int it = 0; it < 4; it++) {
            int idx = tid + it * 256;
            int blk = idx >> 7, rem = idx & 127;
            int tl = rem >> 2, j = rem & 3;
            int s = blk >> 2, mtb = blk & 3;
            int row = mtb * 16 + (tl >> 2) + (j & 1) * 8;
            int kc = s * 16 + 2 * ((tl & 3) + (j >> 1) * 4);
            float2 xv = *(const float2*)(X + row * 2048 + k0 + sl * 32 + kc);
            bf16_split2(xv.x, xv.y, xh[idx], xl[idx]);
        }
        // ---- repack raw W slab into k-paired bf16x2 hi/lo ----
        {
            const float* wr = wsr + (sl & 1) * 4352;
#pragma unroll
            for (int i = 0; i < 8; i++) {
                int p = i * 256 + tid;
                int kk = p >> 7, c = p & 127;
                float w0 = wr[(2 * kk) * 136 + c];
                float w1 = wr[(2 * kk + 1) * 136 + c];
                bf16_split2(w0, w1, wh[kk * 136 + c], wl[kk * 136 + c]);
            }
        }
        __syncthreads();

#pragma unroll
        for (int s = 0; s < 2; s++) {
            uint4 Ah = *(const uint4*)(xh + (s * 4 + mt) * 128 + lane * 4);
            uint4 Al = *(const uint4*)(xl + (s * 4 + mt) * 128 + lane * 4);
            const unsigned* whb = wh + (s * 8 + (lane & 3)) * 136
                                + nh * 64 + (lane >> 2);
            const unsigned* wlb = wl + (s * 8 + (lane & 3)) * 136
                                + nh * 64 + (lane >> 2);
#pragma unroll
            for (int nt = 0; nt < 8; nt++) {
                unsigned b0h = whb[nt * 8], b1h = whb[nt * 8 + 4 * 136];
                unsigned b0l = wlb[nt * 8], b1l = wlb[nt * 8 + 4 * 136];
                mma_bf16(acc[nt], Ah.x, Ah.y, Ah.z, Ah.w, b0h, b1h);
                mma_bf16(acc[nt], Ah.x, Ah.y, Ah.z, Ah.w, b0l, b1l);
                mma_bf16(acc[nt], Al.x, Al.y, Al.z, Al.w, b0h, b1h);
            }
        }
        __syncthreads();
        if (sl + 2 < nslab) {
#pragma unroll
            for (int it = 0; it < 4; it++)
                CPA16(sptr(wsr + (sl & 1) * 4352 + srow[it] * 136 + sc4),
                      W + (size_t)(k0 + (sl + 2) * 32 + srow[it]) * Wn + Wc + sc4);
            CPC();
        }
    }
    {
        int r = lane >> 2, c2 = (lane & 3) * 2;
        if (atomic_out) {
#pragma unroll
            for (int nt = 0; nt < 8; nt++) {
                int col = ob + nh * 64 + nt * 8 + c2;
                float* d0 = P + (size_t)(mt * 16 + r) * Pn + col;
                atomicAdd(d0, acc[nt][0]);
                atomicAdd(d0 + 1, acc[nt][1]);
                float* d1 = P + (size_t)(mt * 16 + r + 8) * Pn + col;
                atomicAdd(d1, acc[nt][2]);
                atomicAdd(d1 + 1, acc[nt][3]);
            }
        } else {
#pragma unroll
            for (int nt = 0; nt < 8; nt++) {
                int col = ob + nh * 64 + nt * 8 + c2;
                *(float2*)(P + ((size_t)ks * 64 + mt * 16 + r) * Pn + col) =
                    make_float2(acc[nt][0], acc[nt][1]);
                *(float2*)(P + ((size_t)ks * 64 + mt * 16 + r + 8) * Pn + col) =
                    make_float2(acc[nt][2], acc[nt][3]);
            }
        }
    }
}

// ---------------------------------------------------------------------------
// Reduce QKV k-split partials + fused RoPE (table-based trig — R10 proven).
// ---------------------------------------------------------------------------
__global__ void reduce_rope_kernel() {
    int gid = blockIdx.x * 256 + threadIdx.x;
    if (gid >= 64 * 1536) return;
    int token = gid / 1536;
    int r = gid - token * 1536;
    int t = token & 3;
    const float* P = &g_qkv_part[0][0][0];

    int h, i, c1;
    bool is_q = (r < 1024), is_k = (!is_q && r < 1280);
    if (is_q)      { h = r >> 6;              i = r & 63; c1 = h * 128 + i; }
    else if (is_k) { int rr = r - 1024; h = rr >> 6; i = rr & 63; c1 = 2048 + h * 128 + i; }
    else           { int rr = r - 1280; h = rr >> 6; i = rr & 63; c1 = 2560 + h * 128 + i; }

    float s1 = 0.f, s2 = 0.f;
#pragma unroll
    for (int ks = 0; ks < QKV_KS; ks++) {
        const float* row = P + ((size_t)ks * 64 + token) * 3072;
        s1 += row[c1];
        s2 += row[c1 + 64];
    }
    if (!is_q && !is_k) {
        g_v[token * 512 + h * 128 + i] = s1;
        g_v[token * 512 + h * 128 + i + 64] = s2;
        return;
    }
    float cs = g_cos[t][i], sn = g_sin[t][i];
    float o1 = s1 * cs - s2 * sn;
    float o2 = s1 * sn + s2 * cs;
    if (is_q) {
        g_q[token * 2048 + c1] = o1;
        g_q[token * 2048 + c1 + 64] = o2;
    } else {
        int cc = h * 128 + i;
        g_k[token * 512 + cc] = o1;
        g_k[token * 512 + cc + 64] = o2;
    }
}

// ---------------------------------------------------------------------------
// Attention (EXACT R10 config — 37.9us measured), mma tf32, async KV stream.
// ---------------------------------------------------------------------------
#define ATS 262
#define ATTN_SMEM_FLOATS (2048 + 4192 + 32 + 8704)
#define ATTN_SMEM_BYTES (ATTN_SMEM_FLOATS * 4)

__global__ void __launch_bounds__(256, 3)
attn_kernel(const float* __restrict__ ck, const float* __restrict__ cv) {
    extern __shared__ float sm[];
    float* q_frag = sm;                // [16 ksteps][128]
    float* at_s   = sm + 2048;         // [16][262]
    float* m_s    = at_s + 4192;
    float* l_s    = m_s + 16;
    float* kv_s   = l_s + 16;          // K: 2x4096 ; V: 2x4352

    const int tid = threadIdx.x;
    const int split = blockIdx.x & 7;
    const int pair  = blockIdx.x >> 3;
    const int b = pair >> 2, kvh = pair & 3;
    const float scale = 0.08838834764831845f;
    const int w = tid >> 5, lane = tid & 31;

    const float* cbk = ck + (size_t)(b * 4 + kvh) * 4096 * 128;
    const float* cbv = cv + (size_t)(b * 4 + kvh) * 4096 * 128;

    const int q4 = lane & 3;
    const float* kp[4];
    unsigned kdst[4];
#pragma unroll
    for (int r = 0; r < 4; r++) {
        int key = w * 32 + r * 8 + (lane >> 2);
        int se = split * 256 + key;
        int crow = (se < 4) ? se : se + 2048;
        kp[r] = cbk + (size_t)crow * 128 + q4 * 4;
        int off = (w * 4 + r) * 128 + (q4 >> 1) * 64 + (q4 & 1) * 32
                + (((lane >> 2) ^ q4) & 7) * 4;
        kdst[r] = sptr(kv_s + off);
    }

#pragma unroll
    for (int r = 0; r < 4; r++) CPA16(kdst[r], kp[r]);
    CPC();
#pragma unroll
    for (int r = 0; r < 4; r++) CPA16(kdst[r] + 16384, kp[r] + 16);
    CPC();

#pragma unroll
    for (int i = 0; i < 8; i++) {
        int idx = tid + i * 256;
        int ks = idx >> 7, rem = idx & 127;
        int tl = rem >> 2, j = rem & 3;
        int row = (tl >> 2) + (j & 1) * 8;
        int col = ks * 8 + (tl & 3) + (j >> 1) * 4;
        int hg = row >> 2, t = row & 3;
        float v = g_q[(b * 4 + t) * 2048 + (kvh * 4 + hg) * 128 + col];
        q_frag[idx] = __uint_as_float(f2tf(v));
    }

    float acc[4][4];
#pragma unroll
    for (int i = 0; i < 4; i++)
#pragma unroll
        for (int j = 0; j < 4; j++) acc[i][j] = 0.f;

#pragma unroll 1
    for (int s = 0; s < 8; s++) {
        if (s < 7) CPW1(); else CPW0();
        __syncthreads();
        const float* kb = kv_s + (s & 1) * 4096;
#pragma unroll
        for (int ksl = 0; ksl < 2; ksl++) {
            uint4 A = *(const uint4*)(q_frag + (s * 2 + ksl) * 128 + lane * 4);
#pragma unroll
            for (int nt = 0; nt < 4; nt++) {
                const float* fb = kb + (w * 4 + nt) * 128 + ksl * 64;
                unsigned bb0 = f2tf(
                    fb[((((lane >> 2) ^ (2 * ksl)) & 7) << 2) + (lane & 3)]);
                unsigned bb1 = f2tf(
                    fb[32 + ((((lane >> 2) ^ (2 * ksl + 1)) & 7) << 2) + (lane & 3)]);
                mma_tf32(acc[nt], A.x, A.y, A.z, A.w, bb0, bb1);
            }
        }
        __syncthreads();
        if (s + 2 < 8) {
#pragma unroll
            for (int r = 0; r < 4; r++)
                CPA16(kdst[r] + (s & 1) * 16384, kp[r] + (s + 2) * 16);
            CPC();
        }
    }
    {
        int r0 = lane >> 2, c2 = (lane & 3) * 2;
#pragma unroll
        for (int nt = 0; nt < 4; nt++) {
            int cc = w * 32 + nt * 8 + c2;
            *(float2*)(at_s + r0 * ATS + cc) =
                make_float2(acc[nt][0] * scale, acc[nt][1] * scale);
            *(float2*)(at_s + (r0 + 8) * ATS + cc) =
                make_float2(acc[nt][2] * scale, acc[nt][3] * scale);
        }
    }
    __syncthreads();

#pragma unroll
    for (int rr = 0; rr < 4; rr++) {
        int se = split * 256 + w * 4 + rr;
        int crow = (se < 4) ? se : se + 2048;
        CPA16(sptr(kv_s + (w * 4 + rr) * 136 + lane * 4),
              cbv + (size_t)crow * 128 + lane * 4);
    }
    CPC();
#pragma unroll
    for (int rr = 0; rr < 4; rr++) {
        int se = split * 256 + 32 + w * 4 + rr;
        int crow = (se < 4) ? se : se + 2048;
        CPA16(sptr(kv_s + 4352 + (w * 4 + rr) * 136 + lane * 4),
              cbv + (size_t)crow * 128 + lane * 4);
    }
    CPC();

    {
#pragma unroll
        for (int rr = 0; rr < 2; rr++) {
            int r = w * 2 + rr;
            float* row = at_s + r * ATS;
            float m = -3.0e38f;
            for (int sx = lane; sx < 256; sx += 32) m = fmaxf(m, row[sx]);
#pragma unroll
            for (int off = 16; off; off >>= 1)
                m = fmaxf(m, __shfl_xor_sync(0xffffffffu, m, off));
            float l = 0.f;
            for (int sx = lane; sx < 256; sx += 32) {
                float e = __expf(row[sx] - m);
                row[sx] = __uint_as_float(f2tf(e));
                l += e;
            }
#pragma unroll
            for (int off = 16; off; off >>= 1)
                l += __shfl_xor_sync(0xffffffffu, l, off);
            if (lane == 0) { m_s[r] = m; l_s[r] = l; }
        }
    }

    float oacc[2][4];
#pragma unroll
    for (int i = 0; i < 2; i++)
#pragma unroll
        for (int j = 0; j < 4; j++) oacc[i][j] = 0.f;

#pragma unroll 1
    for (int t = 0; t < 8; t++) {
        if (t < 7) CPW1(); else CPW0();
        __syncthreads();
        const float* vb = kv_s + (t & 1) * 4352;
#pragma unroll
        for (int j = 0; j < 4; j++) {
            const float* pr = at_s + (lane >> 2) * ATS + t * 32 + j * 8 + (lane & 3);
            unsigned a0 = __float_as_uint(pr[0]);
            unsigned a2 = __float_as_uint(pr[4]);
            unsigned a1 = __float_as_uint(pr[8 * ATS]);
            unsigned a3 = __float_as_uint(pr[8 * ATS + 4]);
            const float* vp = vb + (j * 8 + (lane & 3)) * 136 + w * 16 + (lane >> 2);
#pragma unroll
            for (int nt = 0; nt < 2; nt++) {
                unsigned bb0 = f2tf(vp[nt * 8]);
                unsigned bb1 = f2tf(vp[4 * 136 + nt * 8]);
                mma_tf32(oacc[nt], a0, a1, a2, a3, bb0, bb1);
            }
        }
        __syncthreads();
        if (t + 2 < 8) {
#pragma unroll
            for (int rr = 0; rr < 4; rr++) {
                int se = split * 256 + (t + 2) * 32 + w * 4 + rr;
                int crow = (se < 4) ? se : se + 2048;
                CPA16(sptr(kv_s + (t & 1) * 4352 + (w * 4 + rr) * 136 + lane * 4),
                      cbv + (size_t)crow * 128 + lane * 4);
            }
            CPC();
        }
    }

    {
        size_t base = (size_t)(pair * NSPLITS + split) * 16;
        int r0 = lane >> 2, c2 = (lane & 3) * 2;
#pragma unroll
        for (int nt = 0; nt < 2; nt++) {
            int cc = w * 16 + nt * 8 + c2;
            *(float2*)(g_po + (base + r0) * 128 + cc) =
                make_float2(oacc[nt][0], oacc[nt][1]);
            *(float2*)(g_po + (base + r0 + 8) * 128 + cc) =
                make_float2(oacc[nt][2], oacc[nt][3]);
        }
        if (tid < 16) {
            g_pm[base + tid] = m_s[tid];
            g_pl[base + tid] = l_s[tid];
        }
    }
}

// ---------------------------------------------------------------------------
// Combine: merge 8 cached splits + compute the 4 NEW keys exactly (fp32).
// ---------------------------------------------------------------------------
__global__ void combine_kernel() {
    int bidx = blockIdx.x;
    int pair = bidx >> 4, q = bidx & 15;
    int d = threadIdx.x;
    int hg = q >> 2, t = q & 3;
    int b = pair >> 2, kvh = pair & 3;
    int lane = d & 31, w = d >> 5;

    __shared__ float red[4][4];
    __shared__ float sj_s[4];

    const float scale = 0.08838834764831845f;
    float qv = g_q[(b * 4 + t) * 2048 + (kvh * 4 + hg) * 128 + d];

#pragma unroll
    for (int j = 0; j < 4; j++) {
        float s = qv * g_k[(b * 4 + j) * 512 + kvh * 128 + d];
#pragma unroll
        for (int off = 16; off; off >>= 1)
            s += __shfl_xor_sync(0xffffffffu, s, off);
        if (lane == 0) red[w][j] = s;
    }
    __syncthreads();
    if (d < 4)
        sj_s[d] = (red[0][d] + red[1][d] + red[2][d] + red[3][d]) * scale;
    __syncthreads();

    float s0 = sj_s[0], s1 = sj_s[1], s2 = sj_s[2], s3 = sj_s[3];
    float m_new = fmaxf(fmaxf(s0, s1), fmaxf(s2, s3));
    float e0 = __expf(s0 - m_new), e1 = __expf(s1 - m_new);
    float e2 = __expf(s2 - m_new), e3 = __expf(s3 - m_new);
    float l_new = e0 + e1 + e2 + e3;
    float o_new = e0 * g_v[(b * 4 + 0) * 512 + kvh * 128 + d]
                + e1 * g_v[(b * 4 + 1) * 512 + kvh * 128 + d]
                + e2 * g_v[(b * 4 + 2) * 512 + kvh * 128 + d]
                + e3 * g_v[(b * 4 + 3) * 512 + kvh * 128 + d];

    float ms[NSPLITS];
    float M = m_new;
#pragma unroll
    for (int i = 0; i < NSPLITS; i++) {
        ms[i] = g_pm[(pair * NSPLITS + i) * 16 + q];
        M = fmaxf(M, ms[i]);
    }
    float L = 0.f, acc = 0.f;
#pragma unroll
    for (int i = 0; i < NSPLITS; i++) {
        float wgt = __expf(ms[i] - M);
        L += wgt * g_pl[(pair * NSPLITS + i) * 16 + q];
        acc += wgt * g_po[((size_t)(pair * NSPLITS + i) * 16 + q) * 128 + d];
    }
    float wn = __expf(m_new - M);
    L += wn * l_new;
    acc += wn * o_new;
    g_y[(b * 4 + t) * 2048 + (kvh * 4 + hg) * 128 + d] = acc / L;
}

// ---------------------------------------------------------------------------
extern "C" void kernel_launch(void* const* d_in, const int* in_sizes, int n_in,
                              void* d_out, int out_size) {
    const float* x     = (const float*)d_in[0];
    const float* ck    = (const float*)d_in[1];
    const float* cv    = (const float*)d_in[2];
    const float* wq    = (const float*)d_in[3];
    const float* wk    = (const float*)d_in[4];
    const float* wv    = (const float*)d_in[5];
    const float* wproj = (const float*)d_in[6];
    const int*   sp    = (const int*)d_in[7];
    float* out = (float*)d_out;

    float *qkvp, *yp;
    cudaGetSymbolAddress((void**)&qkvp, g_qkv_part);
    cudaGetSymbolAddress((void**)&yp, g_y);

    cudaFuncSetAttribute(attn_kernel,
                         cudaFuncAttributeMaxDynamicSharedMemorySize,
                         ATTN_SMEM_BYTES);
    cudaFuncSetAttribute(gemm_bf16,
                         cudaFuncAttributeMaxDynamicSharedMemorySize,
                         GEMM_SMEM_BYTES);

    // zero the output (accumulated atomically by the proj GEMM)
    cudaMemsetAsync(d_out, 0, (size_t)out_size * sizeof(float));

    rope_table_kernel<<<8, 32>>>(sp);
    gemm_bf16<<<dim3(24, QKV_KS), 256, GEMM_SMEM_BYTES>>>(
        x, wq, wk, wv, qkvp, 3072, 1, 4, 0);
    reduce_rope_kernel<<<384, 256>>>();
    attn_kernel<<<64 * NSPLITS, 256, ATTN_SMEM_BYTES>>>(ck, cv);
    combine_kernel<<<1024, 128>>>();
    gemm_bf16<<<dim3(16, PROJ_KS), 256, GEMM_SMEM_BYTES>>>(
        yp, wproj, wproj, wproj, out, 2048, 0, 4, 1);
}